// round 16
// baseline (speedup 1.0000x reference)
#include <cuda_runtime.h>
#include <cuda_bf16.h>

#define TT 512
#define LL 62
#define KK 64
#define GG 4
#define FULLM 0xffffffffu

__device__ int   g_rank2batch[1024];
__device__ float g_uvec[1024][KK];
__device__ float g_wvec[1024][KK];
__device__ float g_cf[1024];
__device__ float g_cb[1024];

// Counting-sort batches by seq_len ascending; also zero the output scalar.
__global__ __launch_bounds__(1024) void sort_kernel(
    const int* __restrict__ seq_len, int B, float* __restrict__ out)
{
    __shared__ int scan_s[1024];
    __shared__ int cnt[1024];
    const int tid = threadIdx.x;

    if (tid == 0) out[0] = 0.0f;

    scan_s[tid] = 0;
    cnt[tid]    = 0;
    __syncthreads();

    int v = -1;
    if (tid < B) {
        v = min(max(seq_len[tid], 0), 1023);
        atomicAdd(&scan_s[v], 1);
    }
    __syncthreads();

    #pragma unroll
    for (int off = 1; off < 1024; off <<= 1) {
        int x = scan_s[tid];
        if (tid >= off) x += scan_s[tid - off];
        __syncthreads();
        scan_s[tid] = x;
        __syncthreads();
    }

    if (v >= 0) {
        const int base = (v > 0) ? scan_s[v - 1] : 0;
        const int r = base + atomicAdd(&cnt[v], 1);
        g_rank2batch[r] = tid;
    }
}

__device__ __forceinline__ __nv_bfloat162 u32_as_bf2(unsigned int v) {
    __nv_bfloat162 r;
    *reinterpret_cast<unsigned int*>(&r) = v;
    return r;
}

// dot_j = sum_{k=0}^{63} x[k] * Epk[k-pair]; x bf16 in smem (broadcast
// LDS.128), Epk bf16x2 register pairs. Zero rows make padding exact.
__device__ __forceinline__ float dot64h(const __nv_bfloat16* __restrict__ xbuf,
                                        const __nv_bfloat162* __restrict__ Epk) {
    const uint4* up = reinterpret_cast<const uint4*>(xbuf);
    __nv_bfloat162 z; *reinterpret_cast<unsigned int*>(&z) = 0u;
    __nv_bfloat162 a0 = z, a1 = z, a2 = z, a3 = z;
    #pragma unroll
    for (int q = 0; q < 8; ++q) {
        uint4 v = up[q];
        a0 = __hfma2(u32_as_bf2(v.x), Epk[4 * q + 0], a0);
        a1 = __hfma2(u32_as_bf2(v.y), Epk[4 * q + 1], a1);
        a2 = __hfma2(u32_as_bf2(v.z), Epk[4 * q + 2], a2);
        a3 = __hfma2(u32_as_bf2(v.w), Epk[4 * q + 3], a3);
    }
    __nv_bfloat162 s = __hadd2(__hadd2(a0, a1), __hadd2(a2, a3));
    float2 f = __bfloat1622float2(s);
    return f.x + f.y;
}

__global__ __launch_bounds__(KK, 14) void crf_fb_kernel(
    const float* __restrict__ pred,      // [B, T, L]
    const int*   __restrict__ seq_len,   // [B]
    const float* __restrict__ trans)     // [K, K]
{
    // snake-balanced mapping over sorted ranks; fwd/bwd of one batch are
    // adjacent idx (equal work). Partial last group falls back to identity.
    const int s_ = blockIdx.x % 148;
    const int g_ = blockIdx.x / 148;
    int idx = g_ * 148 + ((g_ & 1) ? (147 - s_) : s_);
    if (idx >= 2048) idx = blockIdx.x;
    const int rank = idx >> 1;
    const int dir  = idx & 1;            // 0 = forward half, 1 = backward half
    const int b    = g_rank2batch[rank];

    const int j = threadIdx.x;
    __shared__ __align__(16) __nv_bfloat16 x_sh[2][KK];

    const float* predb = pred + (size_t)b * TT * LL;
    const int    sl    = seq_len[b];
    const int    m     = sl >> 1;        // fwd steps; bwd steps = sl - m >= 1
    const bool   lab   = (j < LL);

    if (dir == 0) {
        // ---------------- forward: alpha_0 .. alpha_m ----------------
        // E column j as k-pairs; rows 62,63 are exp(-10000) = 0.
        __nv_bfloat162 Epk[32];
        #pragma unroll
        for (int p = 0; p < 32; ++p)
            Epk[p] = __floats2bfloat162_rn(__expf(trans[(2 * p) * KK + j]),
                                           __expf(trans[(2 * p + 1) * KK + j]));

        float un = lab ? 1.0f : 0.0f;    // u = exp(alpha - c), c = -1000
        float c  = -1000.0f;
        x_sh[0][j] = __float2bfloat16(un);
        int cur = 0;

        float eA[GG], eB[GG];
        #pragma unroll
        for (int i = 0; i < GG; ++i)     // rows < m + GG <= 260 < TT: no guard
            eA[i] = lab ? __expf(__ldg(&predb[i * LL + j])) : 0.0f;

        int s = 1;
        while (s + GG <= m + 1) {
            #pragma unroll
            for (int i = 0; i < GG; ++i) {
                const int row = s + GG - 1 + i;
                eB[i] = lab ? __expf(__ldg(&predb[row * LL + j])) : 0.0f;
            }
            #pragma unroll
            for (int i = 0; i < GG; ++i) {
                __syncthreads();
                float sc = 1.0f;
                if (i == 0 && s != 1) {  // deferred renorm every GG steps
                    const float u0 = __bfloat162float(x_sh[cur][0]);
                    sc = __frcp_rn(u0);
                    c += __logf(u0);
                }
                const float d = dot64h(x_sh[cur], Epk);
                un = eA[i] * sc * d;
                x_sh[cur ^ 1][j] = __float2bfloat16(un);
                cur ^= 1;
            }
            #pragma unroll
            for (int i = 0; i < GG; ++i) eA[i] = eB[i];
            s += GG;
        }
        const int rem = m + 1 - s;       // 0..GG-1
        #pragma unroll
        for (int i = 0; i < GG - 1; ++i) {
            if (i >= rem) break;
            __syncthreads();
            float sc = 1.0f;
            if (i == 0 && s != 1) {
                const float u0 = __bfloat162float(x_sh[cur][0]);
                sc = __frcp_rn(u0);
                c += __logf(u0);
            }
            const float d = dot64h(x_sh[cur], Epk);
            un = eA[i] * sc * d;
            x_sh[cur ^ 1][j] = __float2bfloat16(un);
            cur ^= 1;
        }
        g_uvec[b][j] = lab ? un : 0.0f;
        if (j == 0) g_cf[b] = c;
    } else {
        // ---------------- backward: beta_sl .. beta_m ----------------
        // E row j as column-pairs. Rows 62,63 -> w stays exactly 0.
        __nv_bfloat162 Epk[32];
        #pragma unroll
        for (int p = 0; p < 32; ++p)
            Epk[p] = __floats2bfloat162_rn(__expf(trans[j * KK + 2 * p]),
                                           __expf(trans[j * KK + 2 * p + 1]));

        // analytic boundary: beta_sl[k] = trans[k][63] in e-domain (label
        // boundary terms are e^{-1000}-suppressed -> exactly 0 in fp32)
        float w = __expf(trans[j * KK + 63]);
        float c = 0.0f;
        int cur = 0;
        const int N = sl - m;            // >= 1

        float eA[GG], eB[GG];
        #pragma unroll
        for (int i = 0; i < GG; ++i) {
            const int row = sl - 1 - i;
            eA[i] = (lab && row >= 0) ? __expf(__ldg(&predb[row * LL + j])) : 0.0f;
        }

        int q = 0;
        while (q + GG <= N) {
            #pragma unroll
            for (int i = 0; i < GG; ++i) {
                const int row = sl - 1 - (q + GG + i);
                eB[i] = (lab && row >= 0) ? __expf(__ldg(&predb[row * LL + j]))
                                          : 0.0f;
            }
            #pragma unroll
            for (int i = 0; i < GG; ++i) {
                float sc = 1.0f;
                if (i == 0 && q != 0) {  // deferred renorm every GG steps
                    const float v0 = __bfloat162float(x_sh[cur ^ 1][0]);
                    sc = __frcp_rn(v0);
                    c += __logf(v0);
                }
                x_sh[cur][j] = __float2bfloat16(eA[i] * sc * w);
                __syncthreads();
                w = dot64h(x_sh[cur], Epk);
                cur ^= 1;
            }
            #pragma unroll
            for (int i = 0; i < GG; ++i) eA[i] = eB[i];
            q += GG;
        }
        const int rem = N - q;           // 0..GG-1
        #pragma unroll
        for (int i = 0; i < GG - 1; ++i) {
            if (i >= rem) break;
            float sc = 1.0f;
            if (i == 0 && q != 0) {
                const float v0 = __bfloat162float(x_sh[cur ^ 1][0]);
                sc = __frcp_rn(v0);
                c += __logf(v0);
            }
            x_sh[cur][j] = __float2bfloat16(eA[i] * sc * w);
            __syncthreads();
            w = dot64h(x_sh[cur], Epk);
            cur ^= 1;
        }
        g_wvec[b][j] = w;
        if (j == 0) g_cb[b] = c;
    }
}

__global__ __launch_bounds__(KK) void combine_kernel(
    const float* __restrict__ pred,
    const int*   __restrict__ ref,
    const int*   __restrict__ seq_len,
    const float* __restrict__ trans,
    float* __restrict__ out)
{
    const int b    = blockIdx.x;
    const int j    = threadIdx.x;
    const int lane = j & 31;
    const int wid  = j >> 5;

    __shared__ float redP[2], redG[2];

    const float* predb = pred + (size_t)b * TT * LL;
    const int*   refb  = ref  + (size_t)b * TT;
    const int    sl    = seq_len[b];

    // logZ = c_f + c_b + log( sum_k u[k] * w[k] )
    float p = g_uvec[b][j] * g_wvec[b][j];
    #pragma unroll
    for (int off = 16; off; off >>= 1)
        p += __shfl_xor_sync(FULLM, p, off);
    if (lane == 0) redP[wid] = p;

    // gold score, exact fp32
    float gold = 0.0f;
    for (int t = j; t < sl; t += KK)
        gold += __ldg(&predb[t * LL + __ldg(&refb[t])]);
    for (int t = j; t <= sl; t += KK) {
        const int from = (t == 0)  ? LL       : __ldg(&refb[t - 1]);
        const int to   = (t == sl) ? (LL + 1) : __ldg(&refb[t]);
        gold += __ldg(&trans[from * KK + to]);
    }
    #pragma unroll
    for (int off = 16; off; off >>= 1)
        gold += __shfl_xor_sync(FULLM, gold, off);
    if (lane == 0) redG[wid] = gold;
    __syncthreads();

    if (j == 0) {
        const float S = redP[0] + redP[1];
        atomicAdd(out, g_cf[b] + g_cb[b] + __logf(S) - (redG[0] + redG[1]));
    }
}

extern "C" void kernel_launch(void* const* d_in, const int* in_sizes, int n_in,
                              void* d_out, int out_size)
{
    const float* pred    = (const float*)d_in[0];
    const int*   ref     = (const int*)d_in[1];
    const int*   seq_len = (const int*)d_in[2];
    const float* trans   = (const float*)d_in[3];
    float*       out     = (float*)d_out;

    const int B = in_sizes[2];   // 1024

    sort_kernel<<<1, 1024>>>(seq_len, B, out);
    crf_fb_kernel<<<2 * B, KK>>>(pred, seq_len, trans);
    combine_kernel<<<B, KK>>>(pred, ref, seq_len, trans, out);
}